// round 1
// baseline (speedup 1.0000x reference)
#include <cuda_runtime.h>
#include <cuda_bf16.h>
#include <cstdint>

// Problem constants
#define B_  32
#define C_  32
#define H_  160
#define W_  160
#define GI  8
#define GJ  8
#define TH  20
#define TW  20
#define NT  (GI*GJ)          // 64 tiles
#define EPS 1e-5f

// Per-(tile,channel) folded BN affine params
__device__ float d_scale[NT * C_];
__device__ float d_shift[NT * C_];

// ---------------------------------------------------------------------------
// Kernel 1: per-(tile, channel) mean/var over (B, 20, 20) = 12800 elements.
// One block per (tile, channel). Folds gamma/beta into scale/shift.
// ---------------------------------------------------------------------------
__global__ __launch_bounds__(256) void bn_stats_kernel(
    const float* __restrict__ x,
    const float* __restrict__ gamma,
    const float* __restrict__ beta)
{
    const int bid = blockIdx.x;           // t*32 + c
    const int t = bid >> 5;
    const int c = bid & 31;
    const int ti = t >> 3, tj = t & 7;

    const float* base = x + (size_t)c * (H_ * W_) + (size_t)(ti * TH) * W_ + tj * TW;
    const size_t bstride = (size_t)C_ * H_ * W_;

    float s = 0.f, s2 = 0.f;
    for (int i = threadIdx.x; i < B_ * TH * TW; i += 256) {
        int b = i / (TH * TW);
        int r = i - b * (TH * TW);
        int y = r / TW, xx = r - y * TW;
        float v = base[(size_t)b * bstride + y * W_ + xx];
        s += v;
        s2 += v * v;
    }

    __shared__ float ss[256], ss2[256];
    ss[threadIdx.x] = s;
    ss2[threadIdx.x] = s2;
    __syncthreads();
    for (int off = 128; off > 0; off >>= 1) {
        if (threadIdx.x < off) {
            ss[threadIdx.x]  += ss[threadIdx.x + off];
            ss2[threadIdx.x] += ss2[threadIdx.x + off];
        }
        __syncthreads();
    }
    if (threadIdx.x == 0) {
        const float invN = 1.f / (float)(B_ * TH * TW);
        float mean = ss[0] * invN;
        float var  = ss2[0] * invN - mean * mean;
        float sc = gamma[bid] * rsqrtf(var + EPS);
        d_scale[bid] = sc;
        d_shift[bid] = beta[bid] - mean * sc;
    }
}

// ---------------------------------------------------------------------------
// Kernel 2: per-(tile, batch) block.
//   smem: h[32 ch][22 rows][24 cols] zero-padded ReLU(BN(x)) tile  (67,584 B)
//         ws[32 oc][32 ic][9]                                      (36,864 B)
//   320 threads; each computes 4 output channels x 10 pixels (half row).
// ---------------------------------------------------------------------------
#define HROWS 22
#define HCOLS 24
#define H_ELEMS (C_ * HROWS * HCOLS)   // 16896
#define W_ELEMS (C_ * C_ * 9)          // 9216
#define SMEM_FLOATS (H_ELEMS + W_ELEMS)
#define SMEM_BYTES (SMEM_FLOATS * 4)   // 104448

__global__ __launch_bounds__(320) void conv_kernel(
    const float* __restrict__ x,
    const float* __restrict__ conv_w,
    const float* __restrict__ conv_b,
    float* __restrict__ out)
{
    extern __shared__ float smem[];
    float* h  = smem;            // [C_][HROWS][HCOLS]
    float* ws = smem + H_ELEMS;  // [oc][ic][9]

    const int bid = blockIdx.x;     // t*32 + b
    const int t = bid >> 5;
    const int b = bid & 31;
    const int ti = t >> 3, tj = t & 7;
    const int tid = threadIdx.x;

    // ---- stage weights for this tile ----
    const float* gw = conv_w + (size_t)t * W_ELEMS;
    for (int i = tid; i < W_ELEMS; i += 320) ws[i] = gw[i];

    // ---- zero padded h, then fill interior with relu(bn(x)) ----
    for (int i = tid; i < H_ELEMS; i += 320) h[i] = 0.f;
    __syncthreads();

    const size_t xbase = ((size_t)b * C_) * (H_ * W_)
                       + (size_t)(ti * TH) * W_ + tj * TW;
    for (int i = tid; i < C_ * TH * TW; i += 320) {
        int c = i / (TH * TW);
        int r = i - c * (TH * TW);
        int y = r / TW, xx = r - y * TW;
        float v = x[xbase + (size_t)c * (H_ * W_) + y * W_ + xx];
        float sc = d_scale[t * C_ + c];
        float sh = d_shift[t * C_ + c];
        float hv = fmaxf(fmaf(v, sc, sh), 0.f);
        h[(c * HROWS + y + 1) * HCOLS + xx + 1] = hv;
    }
    __syncthreads();

    // ---- direct 3x3 conv: thread -> (og = 4 oc's, row, half-row of 10 px) ----
    const int og   = tid / 40;          // 0..7  -> oc base = og*4
    const int rem  = tid - og * 40;
    const int row  = rem >> 1;          // 0..19
    const int half = rem & 1;           // 0..1
    const int cb   = half * 10;

    float acc[4][10];
#pragma unroll
    for (int j = 0; j < 4; j++)
#pragma unroll
        for (int k = 0; k < 10; k++) acc[j][k] = 0.f;

#pragma unroll 1
    for (int ic = 0; ic < C_; ic++) {
#pragma unroll
        for (int dy = 0; dy < 3; dy++) {
            const float* hr = &h[(ic * HROWS + row + dy) * HCOLS + cb];
            float r[12];
#pragma unroll
            for (int k = 0; k < 12; k++) r[k] = hr[k];
#pragma unroll
            for (int j = 0; j < 4; j++) {
                const float* wp = &ws[((og * 4 + j) * C_ + ic) * 9 + dy * 3];
                float w0 = wp[0], w1 = wp[1], w2 = wp[2];
#pragma unroll
                for (int k = 0; k < 10; k++) {
                    float a = acc[j][k];
                    a = fmaf(w0, r[k],     a);
                    a = fmaf(w1, r[k + 1], a);
                    a = fmaf(w2, r[k + 2], a);
                    acc[j][k] = a;
                }
            }
        }
    }

    // ---- epilogue: + conv bias + residual (raw x), write out ----
#pragma unroll
    for (int j = 0; j < 4; j++) {
        const int oc = og * 4 + j;
        const float cbv = conv_b[t * C_ + oc];
        const size_t o = ((size_t)b * C_ + oc) * (H_ * W_)
                       + (size_t)(ti * TH + row) * W_ + tj * TW + cb;
#pragma unroll
        for (int k = 0; k < 10; k++) {
            out[o + k] = acc[j][k] + cbv + x[o + k];
        }
    }
}

// ---------------------------------------------------------------------------
extern "C" void kernel_launch(void* const* d_in, const int* in_sizes, int n_in,
                              void* d_out, int out_size)
{
    const float* x      = (const float*)d_in[0];
    const float* gamma  = (const float*)d_in[1];
    const float* beta   = (const float*)d_in[2];
    const float* conv_w = (const float*)d_in[3];
    const float* conv_b = (const float*)d_in[4];
    float* out = (float*)d_out;

    bn_stats_kernel<<<NT * C_, 256>>>(x, gamma, beta);

    cudaFuncSetAttribute(conv_kernel,
                         cudaFuncAttributeMaxDynamicSharedMemorySize, SMEM_BYTES);
    conv_kernel<<<NT * B_, 320, SMEM_BYTES>>>(x, conv_w, conv_b, out);
}

// round 2
// speedup vs baseline: 1.0285x; 1.0285x over previous
#include <cuda_runtime.h>
#include <cstdint>

// Problem constants
#define B_  32
#define C_  32
#define H_  160
#define W_  160
#define TH  20
#define TW  20
#define NT  64
#define EPS 1e-5f

typedef unsigned long long u64;

// Per-(tile,channel) folded BN affine params
__device__ float d_scale[NT * C_];
__device__ float d_shift[NT * C_];

// ---- packed f32x2 helpers (sm_103a) ----
__device__ __forceinline__ u64 pack2(float lo, float hi) {
    u64 r; asm("mov.b64 %0, {%1,%2};" : "=l"(r) : "f"(lo), "f"(hi)); return r;
}
__device__ __forceinline__ u64 ffma2(u64 a, u64 b, u64 c) {
    u64 d; asm("fma.rn.f32x2 %0, %1, %2, %3;" : "=l"(d) : "l"(a), "l"(b), "l"(c)); return d;
}
__device__ __forceinline__ u64 add2(u64 a, u64 b) {
    u64 r; asm("add.rn.f32x2 %0, %1, %2;" : "=l"(r) : "l"(a), "l"(b)); return r;
}
// {a.hi, b.lo}
__device__ __forceinline__ u64 mid2(u64 a, u64 b) {
    u64 r;
    asm("{\n\t.reg .b32 al, ah, bl, bh;\n\t"
        "mov.b64 {al, ah}, %1;\n\t"
        "mov.b64 {bl, bh}, %2;\n\t"
        "mov.b64 %0, {ah, bl};\n\t}"
        : "=l"(r) : "l"(a), "l"(b));
    return r;
}

// ---------------------------------------------------------------------------
// Kernel 1: per-(tile, channel) mean/var over (B, 20, 20); float4 loads.
// ---------------------------------------------------------------------------
__global__ __launch_bounds__(256) void bn_stats_kernel(
    const float* __restrict__ x,
    const float* __restrict__ gamma,
    const float* __restrict__ beta)
{
    const int bid = blockIdx.x;           // t*32 + c
    const int t = bid >> 5;
    const int c = bid & 31;
    const int ti = t >> 3, tj = t & 7;

    const float* base = x + (size_t)c * (H_ * W_) + (size_t)(ti * TH) * W_ + tj * TW;
    const size_t bstride = (size_t)C_ * H_ * W_;

    float s = 0.f, s2 = 0.f;
    // B*20 rows x 5 float4 chunks = 3200 vector loads
    for (int i = threadIdx.x; i < B_ * TH * 5; i += 256) {
        int b = i / (TH * 5);
        int r = i - b * (TH * 5);
        int y = r / 5, xq = r - y * 5;
        float4 v = *reinterpret_cast<const float4*>(
            &base[(size_t)b * bstride + y * W_ + xq * 4]);
        s  += (v.x + v.y) + (v.z + v.w);
        s2 += (v.x * v.x + v.y * v.y) + (v.z * v.z + v.w * v.w);
    }

    __shared__ float ss[256], ss2[256];
    ss[threadIdx.x] = s;
    ss2[threadIdx.x] = s2;
    __syncthreads();
    for (int off = 128; off > 0; off >>= 1) {
        if (threadIdx.x < off) {
            ss[threadIdx.x]  += ss[threadIdx.x + off];
            ss2[threadIdx.x] += ss2[threadIdx.x + off];
        }
        __syncthreads();
    }
    if (threadIdx.x == 0) {
        const float invN = 1.f / (float)(B_ * TH * TW);
        float mean = ss[0] * invN;
        float var  = ss2[0] * invN - mean * mean;
        float sc = gamma[bid] * rsqrtf(var + EPS);
        d_scale[bid] = sc;
        d_shift[bid] = beta[bid] - mean * sc;
    }
}

// ---------------------------------------------------------------------------
// Kernel 2: per-(tile, batch) block; packed f32x2 direct 3x3 conv.
//   smem: h[32][22][24] padded ReLU(BN(x)) tile
//         ws[ic*9+tap][32 oc]  (oc-contiguous so 4 ocs load as LDS.128)
// ---------------------------------------------------------------------------
#define HROWS 22
#define HCOLS 24
#define H_ELEMS (C_ * HROWS * HCOLS)   // 16896
#define W_ELEMS (C_ * C_ * 9)          // 9216
#define SMEM_BYTES ((H_ELEMS + W_ELEMS) * 4)   // 104448

__global__ __launch_bounds__(320, 2) void conv_kernel(
    const float* __restrict__ x,
    const float* __restrict__ conv_w,
    const float* __restrict__ conv_b,
    float* __restrict__ out)
{
    extern __shared__ float smem[];
    float* h  = smem;            // [C_][HROWS][HCOLS]
    float* ws = smem + H_ELEMS;  // [(ic*9+tap)][oc]

    const int bid = blockIdx.x;     // t*32 + b
    const int t = bid >> 5;
    const int b = bid & 31;
    const int ti = t >> 3, tj = t & 7;
    const int tid = threadIdx.x;

    // ---- stage weights, transposed to [ic*9+tap][oc] ----
    const float* gw = conv_w + (size_t)t * W_ELEMS;   // [oc][ic][9]
    for (int i = tid; i < W_ELEMS; i += 320) {
        int tap_idx = i >> 5;        // ic*9+tap
        int oc = i & 31;
        ws[i] = gw[(size_t)oc * 288 + tap_idx];
    }

    // ---- zero padded h, fill interior with relu(bn(x)) via float4 loads ----
    for (int i = tid; i < H_ELEMS; i += 320) h[i] = 0.f;
    __syncthreads();

    const size_t xbase = ((size_t)b * C_) * (H_ * W_)
                       + (size_t)(ti * TH) * W_ + tj * TW;
    for (int i = tid; i < C_ * TH * 5; i += 320) {
        int c = i / 100;
        int r = i - c * 100;
        int y = r / 5, xq = r - y * 5;
        float4 v = *reinterpret_cast<const float4*>(
            &x[xbase + (size_t)c * (H_ * W_) + y * W_ + xq * 4]);
        float sc = d_scale[t * C_ + c];
        float sh = d_shift[t * C_ + c];
        float* hp = &h[(c * HROWS + y + 1) * HCOLS + xq * 4 + 1];
        hp[0] = fmaxf(fmaf(v.x, sc, sh), 0.f);
        hp[1] = fmaxf(fmaf(v.y, sc, sh), 0.f);
        hp[2] = fmaxf(fmaf(v.z, sc, sh), 0.f);
        hp[3] = fmaxf(fmaf(v.w, sc, sh), 0.f);
    }
    __syncthreads();

    // ---- thread -> (og = 4 oc's, row, half-row = 5 pixel-pairs) ----
    const int og   = tid / 40;          // 0..7  -> oc base = og*4
    const int rem  = tid - og * 40;
    const int row  = rem >> 1;          // 0..19
    const int half = rem & 1;           // 0..1
    const int cb   = half * 10;

    u64 acc[4][5];
#pragma unroll
    for (int j = 0; j < 4; j++)
#pragma unroll
        for (int k = 0; k < 5; k++) acc[j][k] = 0ull;

    const float4* wsv = reinterpret_cast<const float4*>(ws);

#pragma unroll 1
    for (int ic = 0; ic < C_; ic++) {
        const float* hbase = &h[(ic * HROWS + row) * HCOLS + cb];
#pragma unroll
        for (int dy = 0; dy < 3; dy++) {
            // 12 floats = 6 aligned 8B pair loads
            const u64* hp = reinterpret_cast<const u64*>(hbase + dy * HCOLS);
            u64 p0 = hp[0], p1 = hp[1], p2 = hp[2], p3 = hp[3], p4 = hp[4], p5 = hp[5];
            u64 s0 = mid2(p0, p1), s1 = mid2(p1, p2), s2 = mid2(p2, p3),
                s3 = mid2(p3, p4), s4 = mid2(p4, p5);

            // weights: 3 taps x 4 ocs as 3 x LDS.128
            int wrow = (ic * 9 + dy * 3) * 8 + og;   // float4 index
            float4 wa = wsv[wrow];
            float4 wb = wsv[wrow + 8];
            float4 wc = wsv[wrow + 16];
            const float* waf = reinterpret_cast<const float*>(&wa);
            const float* wbf = reinterpret_cast<const float*>(&wb);
            const float* wcf = reinterpret_cast<const float*>(&wc);

#pragma unroll
            for (int j = 0; j < 4; j++) {
                u64 w0 = pack2(waf[j], waf[j]);
                u64 w1 = pack2(wbf[j], wbf[j]);
                u64 w2 = pack2(wcf[j], wcf[j]);
                acc[j][0] = ffma2(w0, p0, acc[j][0]);
                acc[j][0] = ffma2(w1, s0, acc[j][0]);
                acc[j][0] = ffma2(w2, p1, acc[j][0]);
                acc[j][1] = ffma2(w0, p1, acc[j][1]);
                acc[j][1] = ffma2(w1, s1, acc[j][1]);
                acc[j][1] = ffma2(w2, p2, acc[j][1]);
                acc[j][2] = ffma2(w0, p2, acc[j][2]);
                acc[j][2] = ffma2(w1, s2, acc[j][2]);
                acc[j][2] = ffma2(w2, p3, acc[j][2]);
                acc[j][3] = ffma2(w0, p3, acc[j][3]);
                acc[j][3] = ffma2(w1, s3, acc[j][3]);
                acc[j][3] = ffma2(w2, p4, acc[j][3]);
                acc[j][4] = ffma2(w0, p4, acc[j][4]);
                acc[j][4] = ffma2(w1, s4, acc[j][4]);
                acc[j][4] = ffma2(w2, p5, acc[j][4]);
            }
        }
    }

    // ---- epilogue: + conv bias + residual, packed 8B loads/stores ----
#pragma unroll
    for (int j = 0; j < 4; j++) {
        const int oc = og * 4 + j;
        const float cbv = conv_b[t * C_ + oc];
        const u64 cbd = pack2(cbv, cbv);
        const size_t o = ((size_t)b * C_ + oc) * (H_ * W_)
                       + (size_t)(ti * TH + row) * W_ + tj * TW + cb;
        const u64* xp = reinterpret_cast<const u64*>(&x[o]);
        u64* op = reinterpret_cast<u64*>(&out[o]);
#pragma unroll
        for (int k = 0; k < 5; k++) {
            op[k] = add2(add2(acc[j][k], cbd), xp[k]);
        }
    }
}

// ---------------------------------------------------------------------------
extern "C" void kernel_launch(void* const* d_in, const int* in_sizes, int n_in,
                              void* d_out, int out_size)
{
    const float* x      = (const float*)d_in[0];
    const float* gamma  = (const float*)d_in[1];
    const float* beta   = (const float*)d_in[2];
    const float* conv_w = (const float*)d_in[3];
    const float* conv_b = (const float*)d_in[4];
    float* out = (float*)d_out;

    bn_stats_kernel<<<NT * C_, 256>>>(x, gamma, beta);

    cudaFuncSetAttribute(conv_kernel,
                         cudaFuncAttributeMaxDynamicSharedMemorySize, SMEM_BYTES);
    conv_kernel<<<NT * B_, 320, SMEM_BYTES>>>(x, conv_w, conv_b, out);
}

// round 3
// speedup vs baseline: 1.0290x; 1.0005x over previous
#include <cuda_runtime.h>
#include <cstdint>

// Problem constants
#define B_  32
#define C_  32
#define H_  160
#define W_  160
#define TH  20
#define TW  20
#define NT  64
#define EPS 1e-5f

typedef unsigned long long u64;

// Per-(tile,channel) folded BN affine params
__device__ float d_scale[NT * C_];
__device__ float d_shift[NT * C_];

// ---- packed f32x2 helpers (sm_103a) ----
__device__ __forceinline__ u64 pack2(float lo, float hi) {
    u64 r; asm("mov.b64 %0, {%1,%2};" : "=l"(r) : "f"(lo), "f"(hi)); return r;
}
__device__ __forceinline__ u64 ffma2(u64 a, u64 b, u64 c) {
    u64 d; asm("fma.rn.f32x2 %0, %1, %2, %3;" : "=l"(d) : "l"(a), "l"(b), "l"(c)); return d;
}
__device__ __forceinline__ u64 add2(u64 a, u64 b) {
    u64 r; asm("add.rn.f32x2 %0, %1, %2;" : "=l"(r) : "l"(a), "l"(b)); return r;
}
// {a.hi, b.lo}
__device__ __forceinline__ u64 mid2(u64 a, u64 b) {
    u64 r;
    asm("{\n\t.reg .b32 al, ah, bl, bh;\n\t"
        "mov.b64 {al, ah}, %1;\n\t"
        "mov.b64 {bl, bh}, %2;\n\t"
        "mov.b64 %0, {ah, bl};\n\t}"
        : "=l"(r) : "l"(a), "l"(b));
    return r;
}

// ---------------------------------------------------------------------------
// Kernel 1: per-(tile, channel) mean/var over (B, 20, 20); float4 loads.
// ---------------------------------------------------------------------------
__global__ __launch_bounds__(256) void bn_stats_kernel(
    const float* __restrict__ x,
    const float* __restrict__ gamma,
    const float* __restrict__ beta)
{
    const int bid = blockIdx.x;           // t*32 + c
    const int t = bid >> 5;
    const int c = bid & 31;
    const int ti = t >> 3, tj = t & 7;

    const float* base = x + (size_t)c * (H_ * W_) + (size_t)(ti * TH) * W_ + tj * TW;
    const size_t bstride = (size_t)C_ * H_ * W_;

    float s = 0.f, s2 = 0.f;
    // B*20 rows x 5 float4 chunks = 3200 vector loads
    for (int i = threadIdx.x; i < B_ * TH * 5; i += 256) {
        int b = i / (TH * 5);
        int r = i - b * (TH * 5);
        int y = r / 5, xq = r - y * 5;
        float4 v = *reinterpret_cast<const float4*>(
            &base[(size_t)b * bstride + y * W_ + xq * 4]);
        s  += (v.x + v.y) + (v.z + v.w);
        s2 += (v.x * v.x + v.y * v.y) + (v.z * v.z + v.w * v.w);
    }

    __shared__ float ss[256], ss2[256];
    ss[threadIdx.x] = s;
    ss2[threadIdx.x] = s2;
    __syncthreads();
    for (int off = 128; off > 0; off >>= 1) {
        if (threadIdx.x < off) {
            ss[threadIdx.x]  += ss[threadIdx.x + off];
            ss2[threadIdx.x] += ss2[threadIdx.x + off];
        }
        __syncthreads();
    }
    if (threadIdx.x == 0) {
        const float invN = 1.f / (float)(B_ * TH * TW);
        float mean = ss[0] * invN;
        float var  = ss2[0] * invN - mean * mean;
        float sc = gamma[bid] * rsqrtf(var + EPS);
        d_scale[bid] = sc;
        d_shift[bid] = beta[bid] - mean * sc;
    }
}

// ---------------------------------------------------------------------------
// Kernel 2: per-(tile, batch) block; packed f32x2 direct 3x3 conv.
//   smem: h[32][22][24] padded ReLU(BN(x)) tile
//         ws[ic*9+tap][32 oc]  (oc-contiguous so 4 ocs load as LDS.128)
// ---------------------------------------------------------------------------
#define HROWS 22
#define HCOLS 24
#define H_ELEMS (C_ * HROWS * HCOLS)   // 16896
#define W_ELEMS (C_ * C_ * 9)          // 9216
#define SMEM_BYTES ((H_ELEMS + W_ELEMS) * 4)   // 104448

__global__ __launch_bounds__(320, 2) void conv_kernel(
    const float* __restrict__ x,
    const float* __restrict__ conv_w,
    const float* __restrict__ conv_b,
    float* __restrict__ out)
{
    extern __shared__ float smem[];
    float* h  = smem;            // [C_][HROWS][HCOLS]
    float* ws = smem + H_ELEMS;  // [(ic*9+tap)][oc]

    const int bid = blockIdx.x;     // t*32 + b
    const int t = bid >> 5;
    const int b = bid & 31;
    const int ti = t >> 3, tj = t & 7;
    const int tid = threadIdx.x;

    // ---- stage weights, transposed to [ic*9+tap][oc] ----
    const float* gw = conv_w + (size_t)t * W_ELEMS;   // [oc][ic][9]
    for (int i = tid; i < W_ELEMS; i += 320) {
        int tap_idx = i >> 5;        // ic*9+tap
        int oc = i & 31;
        ws[i] = gw[(size_t)oc * 288 + tap_idx];
    }

    // ---- zero padded h, fill interior with relu(bn(x)) via float4 loads ----
    for (int i = tid; i < H_ELEMS; i += 320) h[i] = 0.f;
    __syncthreads();

    const size_t xbase = ((size_t)b * C_) * (H_ * W_)
                       + (size_t)(ti * TH) * W_ + tj * TW;
    for (int i = tid; i < C_ * TH * 5; i += 320) {
        int c = i / 100;
        int r = i - c * 100;
        int y = r / 5, xq = r - y * 5;
        float4 v = *reinterpret_cast<const float4*>(
            &x[xbase + (size_t)c * (H_ * W_) + y * W_ + xq * 4]);
        float sc = d_scale[t * C_ + c];
        float sh = d_shift[t * C_ + c];
        float* hp = &h[(c * HROWS + y + 1) * HCOLS + xq * 4 + 1];
        hp[0] = fmaxf(fmaf(v.x, sc, sh), 0.f);
        hp[1] = fmaxf(fmaf(v.y, sc, sh), 0.f);
        hp[2] = fmaxf(fmaf(v.z, sc, sh), 0.f);
        hp[3] = fmaxf(fmaf(v.w, sc, sh), 0.f);
    }
    __syncthreads();

    // ---- thread -> (og = 4 oc's, row, half-row = 5 pixel-pairs) ----
    const int og   = tid / 40;          // 0..7  -> oc base = og*4
    const int rem  = tid - og * 40;
    const int row  = rem >> 1;          // 0..19
    const int half = rem & 1;           // 0..1
    const int cb   = half * 10;

    u64 acc[4][5];
#pragma unroll
    for (int j = 0; j < 4; j++)
#pragma unroll
        for (int k = 0; k < 5; k++) acc[j][k] = 0ull;

    const float4* wsv = reinterpret_cast<const float4*>(ws);

#pragma unroll 1
    for (int ic = 0; ic < C_; ic++) {
        const float* hbase = &h[(ic * HROWS + row) * HCOLS + cb];
#pragma unroll
        for (int dy = 0; dy < 3; dy++) {
            // 12 floats = 6 aligned 8B pair loads
            const u64* hp = reinterpret_cast<const u64*>(hbase + dy * HCOLS);
            u64 p0 = hp[0], p1 = hp[1], p2 = hp[2], p3 = hp[3], p4 = hp[4], p5 = hp[5];
            u64 s0 = mid2(p0, p1), s1 = mid2(p1, p2), s2 = mid2(p2, p3),
                s3 = mid2(p3, p4), s4 = mid2(p4, p5);

            // weights: 3 taps x 4 ocs as 3 x LDS.128
            int wrow = (ic * 9 + dy * 3) * 8 + og;   // float4 index
            float4 wa = wsv[wrow];
            float4 wb = wsv[wrow + 8];
            float4 wc = wsv[wrow + 16];
            const float* waf = reinterpret_cast<const float*>(&wa);
            const float* wbf = reinterpret_cast<const float*>(&wb);
            const float* wcf = reinterpret_cast<const float*>(&wc);

#pragma unroll
            for (int j = 0; j < 4; j++) {
                u64 w0 = pack2(waf[j], waf[j]);
                u64 w1 = pack2(wbf[j], wbf[j]);
                u64 w2 = pack2(wcf[j], wcf[j]);
                acc[j][0] = ffma2(w0, p0, acc[j][0]);
                acc[j][0] = ffma2(w1, s0, acc[j][0]);
                acc[j][0] = ffma2(w2, p1, acc[j][0]);
                acc[j][1] = ffma2(w0, p1, acc[j][1]);
                acc[j][1] = ffma2(w1, s1, acc[j][1]);
                acc[j][1] = ffma2(w2, p2, acc[j][1]);
                acc[j][2] = ffma2(w0, p2, acc[j][2]);
                acc[j][2] = ffma2(w1, s2, acc[j][2]);
                acc[j][2] = ffma2(w2, p3, acc[j][2]);
                acc[j][3] = ffma2(w0, p3, acc[j][3]);
                acc[j][3] = ffma2(w1, s3, acc[j][3]);
                acc[j][3] = ffma2(w2, p4, acc[j][3]);
                acc[j][4] = ffma2(w0, p4, acc[j][4]);
                acc[j][4] = ffma2(w1, s4, acc[j][4]);
                acc[j][4] = ffma2(w2, p5, acc[j][4]);
            }
        }
    }

    // ---- epilogue: + conv bias + residual, packed 8B loads/stores ----
#pragma unroll
    for (int j = 0; j < 4; j++) {
        const int oc = og * 4 + j;
        const float cbv = conv_b[t * C_ + oc];
        const u64 cbd = pack2(cbv, cbv);
        const size_t o = ((size_t)b * C_ + oc) * (H_ * W_)
                       + (size_t)(ti * TH + row) * W_ + tj * TW + cb;
        const u64* xp = reinterpret_cast<const u64*>(&x[o]);
        u64* op = reinterpret_cast<u64*>(&out[o]);
#pragma unroll
        for (int k = 0; k < 5; k++) {
            op[k] = add2(add2(acc[j][k], cbd), xp[k]);
        }
    }
}

// ---------------------------------------------------------------------------
extern "C" void kernel_launch(void* const* d_in, const int* in_sizes, int n_in,
                              void* d_out, int out_size)
{
    const float* x      = (const float*)d_in[0];
    const float* gamma  = (const float*)d_in[1];
    const float* beta   = (const float*)d_in[2];
    const float* conv_w = (const float*)d_in[3];
    const float* conv_b = (const float*)d_in[4];
    float* out = (float*)d_out;

    bn_stats_kernel<<<NT * C_, 256>>>(x, gamma, beta);

    cudaFuncSetAttribute(conv_kernel,
                         cudaFuncAttributeMaxDynamicSharedMemorySize, SMEM_BYTES);
    conv_kernel<<<NT * B_, 320, SMEM_BYTES>>>(x, conv_w, conv_b, out);
}

// round 5
// speedup vs baseline: 1.7943x; 1.7437x over previous
#include <cuda_runtime.h>
#include <cuda_bf16.h>
#include <cstdint>

#define B_  32
#define C_  32
#define H_  160
#define W_  160
#define TH  20
#define TW  20
#define NT  64
#define EPS 1e-5f
#define HW  (H_ * W_)        // 25600

// Padded h tile: 22 rows x 24 cols = 528 pixel-rows, each 128B (32ch hi bf16 | 32ch lo bf16)
#define H_BYTES (528 * 128)            // 67584
#define W_BYTES (9 * 32 * 128)         // 36864 (rows = tap*32+ic, [hi oc0-31 | lo oc0-31])
#define SMEM_REQ (1024 + H_BYTES + W_BYTES)

__device__ float d_scale[NT * C_];
__device__ float d_shift[NT * C_];
// Pre-split, pre-swizzled weights: row = tap*32+ic, col bytes = [hi oc*2 | 64 + lo oc*2]
__device__ __align__(16) __nv_bfloat16 g_w2[NT][288 * 64];

__device__ __forceinline__ uint32_t sw128(uint32_t o) { return o ^ ((o >> 3) & 0x70u); }

__device__ __forceinline__ uint32_t smem_u32(const void* p) {
    uint32_t a;
    asm("{ .reg .u64 t; cvta.to.shared.u64 t, %1; cvt.u32.u64 %0, t; }" : "=r"(a) : "l"(p));
    return a;
}

__device__ __forceinline__ void ldm_x4(uint32_t addr,
                                       uint32_t& r0, uint32_t& r1,
                                       uint32_t& r2, uint32_t& r3) {
    asm volatile("ldmatrix.sync.aligned.m8n8.x4.shared.b16 {%0,%1,%2,%3}, [%4];"
                 : "=r"(r0), "=r"(r1), "=r"(r2), "=r"(r3) : "r"(addr));
}
__device__ __forceinline__ void ldm_x4_t(uint32_t addr,
                                         uint32_t& r0, uint32_t& r1,
                                         uint32_t& r2, uint32_t& r3) {
    asm volatile("ldmatrix.sync.aligned.m8n8.x4.trans.shared.b16 {%0,%1,%2,%3}, [%4];"
                 : "=r"(r0), "=r"(r1), "=r"(r2), "=r"(r3) : "r"(addr));
}
__device__ __forceinline__ void mma16816(float* d, uint32_t a0, uint32_t a1,
                                         uint32_t a2, uint32_t a3,
                                         uint32_t b0, uint32_t b1) {
    asm volatile(
        "mma.sync.aligned.m16n8k16.row.col.f32.bf16.bf16.f32 "
        "{%0,%1,%2,%3},{%4,%5,%6,%7},{%8,%9},{%0,%1,%2,%3};"
        : "+f"(d[0]), "+f"(d[1]), "+f"(d[2]), "+f"(d[3])
        : "r"(a0), "r"(a1), "r"(a2), "r"(a3), "r"(b0), "r"(b1));
}

// ---------------------------------------------------------------------------
// Kernel 1: BN stats per (tile, channel=oc) + weight hi/lo split into g_w2.
// ---------------------------------------------------------------------------
__global__ __launch_bounds__(256) void bn_stats_kernel(
    const float* __restrict__ x,
    const float* __restrict__ gamma,
    const float* __restrict__ beta,
    const float* __restrict__ conv_w)
{
    const int bid = blockIdx.x;           // t*32 + c
    const int t = bid >> 5;
    const int c = bid & 31;
    const int ti = t >> 3, tj = t & 7;

    const float* base = x + (size_t)c * HW + (size_t)(ti * TH) * W_ + tj * TW;
    const size_t bstride = (size_t)C_ * HW;

    float s = 0.f, s2 = 0.f;
    for (int i = threadIdx.x; i < B_ * TH * 5; i += 256) {
        int b = i / (TH * 5);
        int r = i - b * (TH * 5);
        int y = r / 5, xq = r - y * 5;
        float4 v = *reinterpret_cast<const float4*>(
            &base[(size_t)b * bstride + y * W_ + xq * 4]);
        s  += (v.x + v.y) + (v.z + v.w);
        s2 += (v.x * v.x + v.y * v.y) + (v.z * v.z + v.w * v.w);
    }

    // weight split for oc = c: rows = tap*32 + ic, col = oc
    for (int i = threadIdx.x; i < 288; i += 256) {
        int ic = i / 9, tap = i - ic * 9;
        float w = conv_w[(((size_t)t * C_ + c) * C_ + ic) * 9 + tap];
        __nv_bfloat16 hi = __float2bfloat16(w);
        __nv_bfloat16 lo = __float2bfloat16(w - __bfloat162float(hi));
        uint32_t row = (uint32_t)(tap * 32 + ic);
        g_w2[t][sw128(row * 128 + c * 2) >> 1]      = hi;
        g_w2[t][sw128(row * 128 + 64 + c * 2) >> 1] = lo;
    }

    __shared__ float ss[256], ss2[256];
    ss[threadIdx.x] = s;
    ss2[threadIdx.x] = s2;
    __syncthreads();
    for (int off = 128; off > 0; off >>= 1) {
        if (threadIdx.x < off) {
            ss[threadIdx.x]  += ss[threadIdx.x + off];
            ss2[threadIdx.x] += ss2[threadIdx.x + off];
        }
        __syncthreads();
    }
    if (threadIdx.x == 0) {
        const float invN = 1.f / (float)(B_ * TH * TW);
        float mean = ss[0] * invN;
        float var  = ss2[0] * invN - mean * mean;
        float sc = gamma[bid] * rsqrtf(var + EPS);
        d_scale[bid] = sc;
        d_shift[bid] = beta[bid] - mean * sc;
    }
}

// ---------------------------------------------------------------------------
// Kernel 2: per-(tile, batch) implicit-GEMM 3x3 conv via mma.sync bf16 hi/lo.
// ---------------------------------------------------------------------------
__global__ __launch_bounds__(256, 2) void conv_kernel(
    const float* __restrict__ x,
    const float* __restrict__ conv_b,
    float* __restrict__ out)
{
    extern __shared__ char smem[];
    const uint32_t sbase = smem_u32(smem);
    const uint32_t hb = (sbase + 1023u) & ~1023u;
    const uint32_t wb = hb + H_BYTES;
    char* hptr = smem + (hb - sbase);
    char* wptr = smem + (wb - sbase);

    const int bid = blockIdx.x;     // t*32 + b
    const int t = bid >> 5;
    const int b = bid & 31;
    const int ti = t >> 3, tj = t & 7;
    const int tid = threadIdx.x;
    const int warp = tid >> 5;
    const int lane = tid & 31;

    // ---- zero h region (padding must be 0) ----
    {
        uint4 z = make_uint4(0, 0, 0, 0);
        uint4* hz = reinterpret_cast<uint4*>(hptr);
        for (int i = tid; i < H_BYTES / 16; i += 256) hz[i] = z;
    }

    // ---- copy pre-split weights (already in swizzled layout) ----
    {
        const uint4* gsrc = reinterpret_cast<const uint4*>(g_w2[t]);
        uint4* wdst = reinterpret_cast<uint4*>(wptr);
        for (int i = tid; i < W_BYTES / 16; i += 256) wdst[i] = gsrc[i];
    }
    __syncthreads();

    // ---- load x tile, BN+ReLU, split to bf16 hi/lo, store swizzled ----
    const size_t xtile = ((size_t)b * C_) * HW + (size_t)(ti * TH) * W_ + tj * TW;
    for (int i = tid; i < C_ * TH * 5; i += 256) {
        int c = i / 100;
        int rr = i - c * 100;
        int y = rr / 5, xq = rr - y * 5;
        float4 v = *reinterpret_cast<const float4*>(
            &x[xtile + (size_t)c * HW + y * W_ + xq * 4]);
        float sc = d_scale[t * C_ + c];
        float sh = d_shift[t * C_ + c];
        int row0 = (y + 1) * 24 + xq * 4 + 1;
        float vv[4] = {v.x, v.y, v.z, v.w};
#pragma unroll
        for (int k = 0; k < 4; k++) {
            float f = fmaxf(fmaf(vv[k], sc, sh), 0.f);
            __nv_bfloat16 hi = __float2bfloat16(f);
            __nv_bfloat16 lo = __float2bfloat16(f - __bfloat162float(hi));
            uint32_t off = (uint32_t)(row0 + k) * 128 + c * 2;
            *reinterpret_cast<__nv_bfloat16*>(hptr + sw128(off))      = hi;
            *reinterpret_cast<__nv_bfloat16*>(hptr + sw128(off + 64)) = lo;
        }
    }
    __syncthreads();

    // ---- warp-level implicit GEMM ----
    const int li   = lane & 7;
    const int sel8 = (lane >> 3) & 1;
    const int selk = (lane >> 4) & 1;
    const int tg   = lane & 3;
    const int g    = lane >> 2;

    // preload bias pairs for this thread's oc columns
    float cb0[4], cb1[4];
#pragma unroll
    for (int j = 0; j < 4; j++) {
        cb0[j] = conv_b[t * C_ + j * 8 + 2 * tg];
        cb1[j] = conv_b[t * C_ + j * 8 + 2 * tg + 1];
    }

    const size_t bb = (size_t)b * C_ * HW;
    const int gtile = (ti * TH) * W_ + tj * TW;

#pragma unroll 1
    for (int mt = warp; mt < 25; mt += 8) {
        float acc[4][4];
#pragma unroll
        for (int j = 0; j < 4; j++)
#pragma unroll
            for (int k = 0; k < 4; k++) acc[j][k] = 0.f;

        const int m0 = mt * 16;
        // A-row base (padded coords) for this lane's ldmatrix row
        const int m = m0 + li + sel8 * 8;
        const int my = m / 20, mx = m - my * 20;
        const int pr0 = my * 24 + mx;

#pragma unroll
        for (int tap = 0; tap < 9; tap++) {
            const int dyx = (tap / 3) * 24 + (tap % 3);
            const int inrow = pr0 + dyx;
            const uint32_t arow = hb + (uint32_t)inrow * 128;
            const uint32_t rx = (uint32_t)(inrow & 7);
            const uint32_t brow = wb + (uint32_t)(tap * 32 + li + sel8 * 8) * 128;
#pragma unroll
            for (int kc = 0; kc < 2; kc++) {
                const uint32_t sa = (uint32_t)(kc * 2 + selk);
                uint32_t ah0, ah1, ah2, ah3, al0, al1, al2, al3;
                ldm_x4(arow + ((sa ^ rx) << 4),        ah0, ah1, ah2, ah3);
                ldm_x4(arow + (((sa + 4) ^ rx) << 4),  al0, al1, al2, al3);

                const uint32_t bro = brow + (uint32_t)(kc * 16) * 128;
                const uint32_t sb0 = (uint32_t)selk;          // n 0-15
                const uint32_t sb1 = (uint32_t)(2 + selk);    // n 16-31
                uint32_t bh[8], bl[8];
                ldm_x4_t(bro + ((sb0 ^ (uint32_t)li) << 4),       bh[0], bh[1], bh[2], bh[3]);
                ldm_x4_t(bro + ((sb1 ^ (uint32_t)li) << 4),       bh[4], bh[5], bh[6], bh[7]);
                ldm_x4_t(bro + (((sb0 + 4) ^ (uint32_t)li) << 4), bl[0], bl[1], bl[2], bl[3]);
                ldm_x4_t(bro + (((sb1 + 4) ^ (uint32_t)li) << 4), bl[4], bl[5], bl[6], bl[7]);

#pragma unroll
                for (int j = 0; j < 4; j++) {
                    mma16816(acc[j], ah0, ah1, ah2, ah3, bh[2 * j], bh[2 * j + 1]);
                    mma16816(acc[j], ah0, ah1, ah2, ah3, bl[2 * j], bl[2 * j + 1]);
                    mma16816(acc[j], al0, al1, al2, al3, bh[2 * j], bh[2 * j + 1]);
                }
            }
        }

        // ---- epilogue: + bias + residual, direct from fragments ----
        const int p0 = m0 + g;
        const int p1 = p0 + 8;
        const int y0 = p0 / 20, x0 = p0 - y0 * 20;
        const int y1 = p1 / 20, x1 = p1 - y1 * 20;
        const size_t pa0 = (size_t)(gtile + y0 * W_ + x0);
        const size_t pa1 = (size_t)(gtile + y1 * W_ + x1);
#pragma unroll
        for (int j = 0; j < 4; j++) {
            const int oc = j * 8 + 2 * tg;
            const size_t a00 = bb + (size_t)oc * HW + pa0;
            const size_t a10 = bb + (size_t)oc * HW + pa1;
            out[a00]      = acc[j][0] + cb0[j] + x[a00];
            out[a00 + HW] = acc[j][1] + cb1[j] + x[a00 + HW];
            out[a10]      = acc[j][2] + cb0[j] + x[a10];
            out[a10 + HW] = acc[j][3] + cb1[j] + x[a10 + HW];
        }
    }
}

// ---------------------------------------------------------------------------
extern "C" void kernel_launch(void* const* d_in, const int* in_sizes, int n_in,
                              void* d_out, int out_size)
{
    const float* x      = (const float*)d_in[0];
    const float* gamma  = (const float*)d_in[1];
    const float* beta   = (const float*)d_in[2];
    const float* conv_w = (const float*)d_in[3];
    const float* conv_b = (const float*)d_in[4];
    float* out = (float*)d_out;

    bn_stats_kernel<<<NT * C_, 256>>>(x, gamma, beta, conv_w);

    cudaFuncSetAttribute(conv_kernel,
                         cudaFuncAttributeMaxDynamicSharedMemorySize, SMEM_REQ);
    conv_kernel<<<NT * B_, 256, SMEM_REQ>>>(x, conv_b, out);
}